// round 16
// baseline (speedup 1.0000x reference)
#include <cuda_runtime.h>
#include <cuda_fp16.h>
#include <math.h>
#include <stdint.h>

#define BB 8
#define DD 512
#define DFF 2048
#define L0 4096
#define UMAX 45
#define LN_EPS 1e-5f

// ------------------- scratch (device globals; no allocs) -------------------
__device__ __align__(16) float g_h  [BB*L0*DD];
__device__ __align__(16) __half g_hh [BB*L0*DD];   // fp16 mirror for attention reads
__device__ __align__(16) float g_x  [BB*L0*DD];
__device__ __align__(16) float g_z  [BB*L0*DD];
__device__ __align__(16) __half g_xhi[BB*L0*DD];
__device__ __align__(16) __half g_xlo[BB*L0*DD];
__device__ __align__(16) __half g_yhi[BB*L0*DFF];
__device__ __align__(16) __half g_w1hi[3*DFF*DD];
__device__ __align__(16) __half g_w2hi[3*DD*DFF];
__device__ __align__(16) __half g_owhi[DD*DD];
__device__ __align__(16) __half g_exhi[BB*L0*64];
__device__ __align__(16) __half g_exlo[BB*L0*64];
__device__ __align__(16) __half g_ewhi[DD*64];
__device__ __align__(16) __half g_ewlo[DD*64];
__device__ __align__(16) float g_M  [BB*8*L0];
__device__ __align__(16) int   g_top[BB*8*UMAX];
__device__ __align__(16) int   g_rowmap[BB*8*L0];
__device__ __align__(16) float g_ctx[BB*8*UMAX*64];
__device__ __align__(16) float g_qmean[BB*8*64];
// split-L ctx partials (max 8 splits)
__device__ __align__(16) float g_pm  [64*8*UMAX];
__device__ __align__(16) float g_ps  [64*8*UMAX];
__device__ __align__(16) float g_pctx[64*8*UMAX*64];
__device__ __align__(16) float g_pq  [64*8*64];

// ------------------- fp16 split helpers -------------------------------------
__device__ __forceinline__ void split_fp16(float v, __half &hi, __half &lo)
{
  hi = __float2half_rn(v);
  lo = __float2half_rn(v - __half2float(hi));
}

// ------------------- threefry2x32 (JAX-compatible) -------------------------
#define TF_R(x0,x1,r) { x0 += x1; x1 = ((x1 << (r)) | (x1 >> (32-(r)))); x1 ^= x0; }
__host__ __device__ __forceinline__ void threefry2x32(unsigned ks0, unsigned ks1,
                                                      unsigned &x0, unsigned &x1)
{
  unsigned ks2 = ks0 ^ ks1 ^ 0x1BD11BDAu;
  x0 += ks0; x1 += ks1;
  TF_R(x0,x1,13) TF_R(x0,x1,15) TF_R(x0,x1,26) TF_R(x0,x1,6)
  x0 += ks1; x1 += ks2 + 1u;
  TF_R(x0,x1,17) TF_R(x0,x1,29) TF_R(x0,x1,16) TF_R(x0,x1,24)
  x0 += ks2; x1 += ks0 + 2u;
  TF_R(x0,x1,13) TF_R(x0,x1,15) TF_R(x0,x1,26) TF_R(x0,x1,6)
  x0 += ks0; x1 += ks1 + 3u;
  TF_R(x0,x1,17) TF_R(x0,x1,29) TF_R(x0,x1,16) TF_R(x0,x1,24)
  x0 += ks1; x1 += ks2 + 4u;
  TF_R(x0,x1,13) TF_R(x0,x1,15) TF_R(x0,x1,26) TF_R(x0,x1,6)
  x0 += ks2; x1 += ks0 + 5u;
}

// ------------------- splits -------------------------------------------------
__global__ void whalf_kernel(const float* __restrict__ w,
                             __half* __restrict__ hi, int n)
{
  int i = blockIdx.x * 256 + threadIdx.x;
  if (i >= n) return;
  hi[i] = __float2half_rn(w[i]);
}

__global__ void xsplit_kernel(const float* __restrict__ w,
                              __half* __restrict__ hi, __half* __restrict__ lo, int n)
{
  int i = blockIdx.x * 256 + threadIdx.x;
  if (i >= n) return;
  __half h, l;
  split_fp16(w[i], h, l);
  hi[i] = h; lo[i] = l;
}

// ------------------- M = max_s qk - sum_s qk / L ----------------------------
// quarter-warp scheme, 2x unrolled: 8 samples in flight (2 per quarter),
// two independent 3-step butterflies interleaved for ILP.
__device__ __forceinline__ float dot8(const float* qv, uint4 t)
{
  const __half2* hp = (const __half2*)&t;
  float2 f0 = __half22float2(hp[0]);
  float2 f1 = __half22float2(hp[1]);
  float2 f2 = __half22float2(hp[2]);
  float2 f3 = __half22float2(hp[3]);
  return qv[0]*f0.x + qv[1]*f0.y + qv[2]*f1.x + qv[3]*f1.y
       + qv[4]*f2.x + qv[5]*f2.y + qv[6]*f3.x + qv[7]*f3.y;
}

__global__ __launch_bounds__(256) void prob_m_kernel(
    const __half* __restrict__ hh, int L, int u, float invL,
    unsigned k0, unsigned k1, int mask)
{
  int bh = blockIdx.y; int b = bh >> 3, hd = bh & 7;
  int warp = threadIdx.x >> 5, lane = threadIdx.x & 31;
  int l = blockIdx.x * 8 + warp;
  const __half* base = hh + (size_t)b * L * DD + hd * 64;
  const int lane8 = lane & 7;
  const int quad  = lane >> 3;
  const __half* base8 = base + lane8 * 8;   // hoisted per-lane column offset

  float qv[8];
  {
    uint4 t = *(const uint4*)(base8 + (size_t)l * DD);
    const __half2* hp = (const __half2*)&t;
    float2 f0 = __half22float2(hp[0]);
    float2 f1 = __half22float2(hp[1]);
    float2 f2 = __half22float2(hp[2]);
    float2 f3 = __half22float2(hp[3]);
    qv[0]=f0.x; qv[1]=f0.y; qv[2]=f1.x; qv[3]=f1.y;
    qv[4]=f2.x; qv[5]=f2.y; qv[6]=f3.x; qv[7]=f3.y;
  }

  // inline threefry (partitionable): bits[t] = y0^y1 of TF(k2,(0,t)), t=l*u+s
  int idxA = 0, idxB = 0;
  {
    unsigned x0 = 0u, x1 = (unsigned)(l * u + lane);
    threefry2x32(k0, k1, x0, x1);
    if (lane < u) idxA = (int)((x0 ^ x1) & (unsigned)mask);
    unsigned y0 = 0u, y1 = (unsigned)(l * u + lane + 32);
    threefry2x32(k0, k1, y0, y1);
    if (lane + 32 < u) idxB = (int)((y0 ^ y1) & (unsigned)mask);
  }

  float mx = -INFINITY, sm = 0.f;
  int s = 0;
  // 8 samples per iteration: two groups of 4, interleaved butterflies
  for (; s + 7 < u; s += 8) {
    int sq0 = s + quad, sq1 = s + 4 + quad;
    int kl0 = __shfl_sync(0xffffffffu, (s < 32) ? idxA : idxB, sq0 & 31);
    int kl1 = __shfl_sync(0xffffffffu, ((s + 4) < 32) ? idxA : idxB, sq1 & 31);
    uint4 t0 = *(const uint4*)(base8 + (size_t)kl0 * DD);
    uint4 t1 = *(const uint4*)(base8 + (size_t)kl1 * DD);
    float p0 = dot8(qv, t0);
    float p1 = dot8(qv, t1);
    #pragma unroll
    for (int o = 4; o; o >>= 1) {
      p0 += __shfl_xor_sync(0xffffffffu, p0, o);
      p1 += __shfl_xor_sync(0xffffffffu, p1, o);
    }
    mx = fmaxf(mx, p0); sm += p0;     // group s..s+3 first (order preserved)
    mx = fmaxf(mx, p1); sm += p1;     // then group s+4..s+7
  }
  // 4 samples
  for (; s + 3 < u; s += 4) {
    int sq = s + quad;
    int kl = __shfl_sync(0xffffffffu, (s < 32) ? idxA : idxB, sq & 31);
    uint4 t = *(const uint4*)(base8 + (size_t)kl * DD);
    float p = dot8(qv, t);
    #pragma unroll
    for (int o = 4; o; o >>= 1) p += __shfl_xor_sync(0xffffffffu, p, o);
    mx = fmaxf(mx, p); sm += p;
  }
  // tail: all quarters compute the same sample; quarter 0 accumulates
  for (; s < u; s++) {
    int kl = __shfl_sync(0xffffffffu, (s < 32) ? idxA : idxB, s & 31);
    uint4 t = *(const uint4*)(base8 + (size_t)kl * DD);
    float p = dot8(qv, t);
    #pragma unroll
    for (int o = 4; o; o >>= 1) p += __shfl_xor_sync(0xffffffffu, p, o);
    if (quad == 0) { mx = fmaxf(mx, p); sm += p; }
  }
  // merge quarters
  #pragma unroll
  for (int o = 8; o <= 16; o <<= 1) {
    mx = fmaxf(mx, __shfl_xor_sync(0xffffffffu, mx, o));
    sm += __shfl_xor_sync(0xffffffffu, sm, o);
  }
  if (lane == 0) g_M[(size_t)bh * L + l] = mx - sm * invL;
}

// ------------------- top-k: tournament argmax (exact, lower-index ties) ----
__global__ __launch_bounds__(256) void topk_kernel(int L, int u)
{
  __shared__ float sM[L0];
  __shared__ float gmax[64];
  __shared__ int   gidx[64];
  int bh = blockIdx.x;
  int tid = threadIdx.x;
  int ngroups = L >> 6;
  for (int l = tid; l < L; l += 256) {
    sM[l] = g_M[(size_t)bh * L + l];
    g_rowmap[(size_t)bh * L + l] = -1;
  }
  __syncthreads();
  if (tid < ngroups) {
    float bv = -INFINITY; int bi = tid * 64;
    #pragma unroll 8
    for (int j = 0; j < 64; j++) {
      float v = sM[tid * 64 + j];
      if (v > bv) { bv = v; bi = tid * 64 + j; }
    }
    gmax[tid] = bv; gidx[tid] = bi;
  }
  __syncthreads();

  if (tid < 32) {
    for (int r = 0; r < u; r++) {
      float bv = -INFINITY; int bi = 0x7fffffff;
      for (int g = tid; g < ngroups; g += 32) {
        float v = gmax[g]; int i = gidx[g];
        if (v > bv || (v == bv && i < bi)) { bv = v; bi = i; }
      }
      #pragma unroll
      for (int o = 16; o; o >>= 1) {
        float v2 = __shfl_xor_sync(0xffffffffu, bv, o);
        int   i2 = __shfl_xor_sync(0xffffffffu, bi, o);
        if (v2 > bv || (v2 == bv && i2 < bi)) { bv = v2; bi = i2; }
      }
      int sel = __shfl_sync(0xffffffffu, bi, 0);
      if (tid == 0) {
        g_top[bh * u + r] = sel;
        g_rowmap[(size_t)bh * L + sel] = r;
        sM[sel] = -INFINITY;
      }
      __syncwarp();
      int gs = sel >> 6;
      int e0 = gs * 64 + tid, e1 = e0 + 32;
      float v0 = sM[e0], v1 = sM[e1];
      float nv; int ni;
      if (v0 >= v1) { nv = v0; ni = e0; } else { nv = v1; ni = e1; }
      if (v0 == v1) { ni = e0; }
      #pragma unroll
      for (int o = 16; o; o >>= 1) {
        float v2 = __shfl_xor_sync(0xffffffffu, nv, o);
        int   i2 = __shfl_xor_sync(0xffffffffu, ni, o);
        if (v2 > nv || (v2 == nv && i2 < ni)) { nv = v2; ni = i2; }
      }
      if (tid == 0) { gmax[gs] = nv; gidx[gs] = ni; }
      __syncwarp();
    }
  }
}

// ------------------- split-L ctx (fp16 key reads; R12 strided form) ---------
// smem floats: qs 3072 | kt 4352 | sc 3072 | ctxs 3072 | rm/rs/rsc 144 | qred 256
#define CTX_SMEM_FLOATS (13568 + 144 + 256)
__global__ __launch_bounds__(256) void ctx_split_kernel(
    const __half* __restrict__ hh, int L, int u, int klen)
{
  extern __shared__ float dsm[];
  float* qs   = dsm;            // stride 64
  float* kt   = dsm + 3072;     // stride 68
  float* sc   = dsm + 7424;     // stride 64
  float* ctxs = dsm + 10496;    // stride 64
  float* rm   = dsm + 13568;
  float* rs   = dsm + 13616;
  float* rsc  = dsm + 13664;
  float* qred = dsm + 13712;    // [4][64]

  int split = blockIdx.x;
  int bh = blockIdx.y; int b = bh >> 3, hd = bh & 7;
  const __half* base = hh + (size_t)b * L * DD + hd * 64;
  int tid = threadIdx.x;
  int kbeg = split * klen;

  for (int e = tid; e < u * 64; e += 256) {
    int r = e >> 6, d = e & 63;
    qs[r * 64 + d] = __half2float(base[(size_t)g_top[bh * u + r] * DD + d]);
    ctxs[e] = 0.f;
  }
  if (tid < u) { rm[tid] = -INFINITY; rs[tid] = 0.f; }
  __syncthreads();

  const int j  = tid & 63;
  const int rg = tid >> 6;
  const int w  = tid >> 5, lane = tid & 31;
  float qacc = 0.f;

  for (int t0 = kbeg; t0 < kbeg + klen; t0 += 64) {
    for (int e = tid; e < 64 * 8; e += 256) {
      int r = e >> 3, c8 = e & 7;
      uint4 v = *(const uint4*)(base + (size_t)(t0 + r) * DD + c8 * 8);
      const __half2* hp = (const __half2*)&v;
      float* kr = kt + r * 68 + c8 * 8;
      #pragma unroll
      for (int q = 0; q < 4; q++) {
        float2 f = __half22float2(hp[q]);
        kr[2 * q] = f.x; kr[2 * q + 1] = f.y;
      }
    }
    __syncthreads();

    #pragma unroll
    for (int r = 0; r < 16; r++) qacc += kt[(rg + r * 4) * 68 + j];

    {
      float kreg[64];
      #pragma unroll
      for (int d = 0; d < 64; d++) kreg[d] = kt[j * 68 + d];
      for (int r = rg; r < u; r += 4) {
        const float* qr = qs + r * 64;
        float dot = 0.f;
        #pragma unroll
        for (int d = 0; d < 64; d++) dot += qr[d] * kreg[d];
        sc[r * 64 + j] = dot * 0.125f;
      }
    }
    __syncthreads();
    for (int r = w; r < u; r += 8) {
      float v0 = sc[r * 64 + lane], v1 = sc[r * 64 + lane + 32];
      float mx = fmaxf(v0, v1);
      #pragma unroll
      for (int o = 16; o; o >>= 1) mx = fmaxf(mx, __shfl_xor_sync(0xffffffffu, mx, o));
      float mold = rm[r];
      float mnew = fmaxf(mold, mx);
      float p0 = __expf(v0 - mnew), p1 = __expf(v1 - mnew);
      float ps = p0 + p1;
      #pragma unroll
      for (int o = 16; o; o >>= 1) ps += __shfl_xor_sync(0xffffffffu, ps, o);
      if (lane == 0) {
        float cold = __expf(mold - mnew);
        rsc[r] = cold;
        rs[r] = rs[r] * cold + ps;
        rm[r] = mnew;
      }
      sc[r * 64 + lane] = p0; sc[r * 64 + lane + 32] = p1;
    }
    __syncthreads();
    for (int r = rg; r < u; r += 4) {
      const float* pr = sc + r * 64;
      float a = 0.f;
      #pragma unroll
      for (int jj = 0; jj < 64; jj++) a += pr[jj] * kt[jj * 68 + j];
      ctxs[r * 64 + j] = ctxs[r * 64 + j] * rsc[r] + a;
    }
    __syncthreads();
  }

  // write partials
  qred[rg * 64 + j] = qacc;
  __syncthreads();
  if (rg == 0)
    g_pq[(bh * 8 + split) * 64 + j] =
      qred[j] + qred[64 + j] + qred[128 + j] + qred[192 + j];
  if (tid < u) {
    g_pm[(bh * 8 + split) * UMAX + tid] = rm[tid];
    g_ps[(bh * 8 + split) * UMAX + tid] = rs[tid];
  }
  for (int e = tid; e < u * 64; e += 256) {
    int r = e >> 6, d = e & 63;
    g_pctx[((size_t)((bh * 8 + split) * UMAX + r)) * 64 + d] = ctxs[r * 64 + d];
  }
}

// ------------------- merge split-L partials ---------------------------------
__global__ __launch_bounds__(256) void ctx_merge_kernel(int L, int u, int nsplit)
{
  int bh = blockIdx.x;
  int tid = threadIdx.x;
  if (tid < 64) {
    float q = 0.f;
    for (int s = 0; s < nsplit; s++) q += g_pq[(bh * 8 + s) * 64 + tid];
    g_qmean[bh * 64 + tid] = q / (float)L;
  }
  for (int e = tid; e < u * 64; e += 256) {
    int r = e >> 6, d = e & 63;
    float M0 = -INFINITY;
    for (int s = 0; s < nsplit; s++)
      M0 = fmaxf(M0, g_pm[(bh * 8 + s) * UMAX + r]);
    float num = 0.f, den = 0.f;
    for (int s = 0; s < nsplit; s++) {
      float c = __expf(g_pm[(bh * 8 + s) * UMAX + r] - M0);
      num += g_pctx[((size_t)((bh * 8 + s) * UMAX + r)) * 64 + d] * c;
      den += g_ps[(bh * 8 + s) * UMAX + r] * c;
    }
    g_ctx[((size_t)(bh * u + r)) * 64 + d] = num / den;
  }
}

// ------------------- block reduce helper (128 threads) ---------------------
__device__ __forceinline__ float blocksum128(float v, float* sred)
{
  #pragma unroll
  for (int o = 16; o; o >>= 1) v += __shfl_xor_sync(0xffffffffu, v, o);
  if ((threadIdx.x & 31) == 0) sred[threadIdx.x >> 5] = v;
  __syncthreads();
  float t = sred[0] + sred[1] + sred[2] + sred[3];
  __syncthreads();
  return t;
}

// ------------------- assemble attention out + residual + LN1 + fp16 hi -----
__global__ __launch_bounds__(128) void assemble_ln1_kernel(
    const float* __restrict__ hin, float* __restrict__ xout,
    __half* __restrict__ xhi,
    const float* __restrict__ gamma, const float* __restrict__ beta,
    int L, int u)
{
  __shared__ float sred[4];
  int row = blockIdx.x;
  int b = row / L, l = row - b * L;
  int tid = threadIdx.x;
  float v[4];
  #pragma unroll
  for (int i = 0; i < 4; i++) {
    int e = i * 128 + tid;
    int hh = e >> 6, dd = e & 63;
    int bh = b * 8 + hh;
    int r = g_rowmap[(size_t)bh * L + l];
    float nv = (r >= 0) ? g_ctx[((size_t)(bh * u + r)) * 64 + dd]
                        : g_qmean[bh * 64 + dd];
    v[i] = hin[(size_t)row * DD + e] + nv;
  }
  float s = blocksum128(v[0] + v[1] + v[2] + v[3], sred);
  float mu = s * (1.0f / 512.0f);
  float vs = 0.f;
  #pragma unroll
  for (int i = 0; i < 4; i++) { float d = v[i] - mu; vs += d * d; }
  vs = blocksum128(vs, sred);
  float rstd = rsqrtf(vs * (1.0f / 512.0f) + LN_EPS);
  #pragma unroll
  for (int i = 0; i < 4; i++) {
    int e = i * 128 + tid;
    float o = (v[i] - mu) * rstd * gamma[e] + beta[e];
    xout[(size_t)row * DD + e] = o;
    xhi[(size_t)row * DD + e] = __float2half_rn(o);
  }
}

// ------------------- fused residual+LN2+distil (layers 0,1) ----------------
__global__ __launch_bounds__(128) void ln2_distil_kernel(
    const float* __restrict__ xin, const float* __restrict__ zin,
    float* __restrict__ outp, __half* __restrict__ outh,
    const float* __restrict__ gamma, const float* __restrict__ beta, int L2)
{
  __shared__ float sred[4];
  int rowo = blockIdx.x;
  int b = rowo / L2, l2 = rowo - b * L2;
  size_t r0 = ((size_t)b * (2 * L2) + 2 * l2);
  int tid = threadIdx.x;
  float o01[4];
  #pragma unroll
  for (int half = 0; half < 2; half++) {
    size_t row = r0 + half;
    float v[4];
    #pragma unroll
    for (int i = 0; i < 4; i++) {
      int e = i * 128 + tid;
      v[i] = xin[row * DD + e] + zin[row * DD + e];
    }
    float s = blocksum128(v[0] + v[1] + v[2] + v[3], sred);
    float mu = s * (1.0f / 512.0f);
    float vs = 0.f;
    #pragma unroll
    for (int i = 0; i < 4; i++) { float d = v[i] - mu; vs += d * d; }
    vs = blocksum128(vs, sred);
    float rstd = rsqrtf(vs * (1.0f / 512.0f) + LN_EPS);
    #pragma unroll
    for (int i = 0; i < 4; i++) {
      int e = i * 128 + tid;
      float o = (v[i] - mu) * rstd * gamma[e] + beta[e];
      if (half == 0) o01[i] = o; else o01[i] = 0.5f * (o01[i] + o);
    }
  }
  #pragma unroll
  for (int i = 0; i < 4; i++) {
    int e = i * 128 + tid;
    outp[(size_t)rowo * DD + e] = o01[i];
    outh[(size_t)rowo * DD + e] = __float2half_rn(o01[i]);
  }
}

// ------------------- residual + LN2 -> fp16 split only (last layer) --------
__global__ __launch_bounds__(128) void ln2_split_kernel(
    const float* __restrict__ xin, const float* __restrict__ zin,
    __half* __restrict__ ohi, __half* __restrict__ olo,
    const float* __restrict__ gamma, const float* __restrict__ beta)
{
  __shared__ float sred[4];
  size_t row = blockIdx.x;
  int tid = threadIdx.x;
  float v[4];
  #pragma unroll
  for (int i = 0; i < 4; i++) {
    int e = i * 128 + tid;
    v[i] = xin[row * DD + e] + zin[row * DD + e];
  }
  float s = blocksum128(v[0] + v[1] + v[2] + v[3], sred);
  float mu = s * (1.0f / 512.0f);
  float vs = 0.f;
  #pragma unroll
  for (int i = 0; i < 4; i++) { float d = v[i] - mu; vs += d * d; }
  vs = blocksum128(vs, sred);
  float rstd = rsqrtf(vs * (1.0f / 512.0f) + LN_EPS);
  #pragma unroll
  for (int i = 0; i < 4; i++) {
    int e = i * 128 + tid;
    float o = (v[i] - mu) * rstd * gamma[e] + beta[e];
    __half h16, l16;
    split_fp16(o, h16, l16);
    ohi[row * DD + e] = h16;
    olo[row * DD + e] = l16;
  }
}

// ------------------- fp16 tensor-core GEMM (1/2/3-pass) ---------------------
#define KC 32                     // k elems per stage
#define LDPB 80                   // padded row stride in BYTES (40 fp16)
#define PLANE_B (128*LDPB)        // 10240 bytes per plane

__device__ __forceinline__ void mma_fp16(float* c, const unsigned* a, const unsigned* b)
{
  asm volatile(
    "mma.sync.aligned.m16n8k16.row.col.f32.f16.f16.f32 "
    "{%0,%1,%2,%3},{%4,%5,%6,%7},{%8,%9},{%0,%1,%2,%3};\n"
    : "+f"(c[0]), "+f"(c[1]), "+f"(c[2]), "+f"(c[3])
    : "r"(a[0]), "r"(a[1]), "r"(a[2]), "r"(a[3]), "r"(b[0]), "r"(b[1]));
}

__device__ __forceinline__ void ldsm4(unsigned* r, const char* sptr)
{
  unsigned addr = (unsigned)__cvta_generic_to_shared(sptr);
  asm volatile("ldmatrix.sync.aligned.m8n8.x4.shared.b16 {%0,%1,%2,%3}, [%4];\n"
    : "=r"(r[0]), "=r"(r[1]), "=r"(r[2]), "=r"(r[3]) : "r"(addr));
}

// EPI 0: Cf = acc + bias (fp32)
// EPI 1: Chi = fp16(gelu(acc + bias))
// EPI 2: Cf = acc + bias + PE (fp32) AND Chh = fp16 copy
// NPASS 1: A_hi x B_hi | NPASS 2: (A_hi+A_lo) x B_hi | NPASS 3: + A_hi x B_lo
template<int EPI, int NPASS>
__global__ __launch_bounds__(256, 2) void mma_gemm(
    const __half* __restrict__ Ahi, const __half* __restrict__ Alo,
    const __half* __restrict__ Bhi, const __half* __restrict__ Blo,
    const float* __restrict__ bias,
    float* __restrict__ Cf, __half* __restrict__ Chi, __half* __restrict__ Chh,
    int M, int N, int K, int Lmask)
{
  constexpr int NPLANES = (NPASS == 3) ? 4 : (NPASS + 1);
  const int STGB = NPLANES * PLANE_B;
  extern __shared__ char smc[];
  const int tid = threadIdx.x;
  const int bm = blockIdx.y * 128, bn = blockIdx.x * 128;
  const int lane = tid & 31;
  const int g = lane >> 2, t4 = lane & 3;
  const int warp = tid >> 5;
  const int wm = warp >> 2, wn = warp & 3;      // warps 2(m) x 4(n)
  const int moff = wm * 64, noff = wn * 32;

  const int aoff = (lane & 15) * LDPB + ((lane & 16) ? 16 : 0);
  const int boff = ((lane & 7) + ((lane & 16) ? 8 : 0)) * LDPB + ((lane & 8) ? 16 : 0);

  float acc[4][4][4];
  #pragma unroll
  for (int i = 0; i < 4; i++)
    #pragma unroll
    for (int j = 0; j < 4; j++)
      #pragma unroll
      for (int q = 0; q < 4; q++) acc[i][j][q] = 0.f;

  const int KT = K / KC;

  #define PREFETCH(kt, s) do {                                                   \
    int k0_ = (kt) * KC;                                                         \
    const char* srcs_[NPLANES];                                                  \
    int np_ = 0;                                                                 \
    srcs_[np_++] = (const char*)(Ahi + (size_t)bm * K + k0_);                    \
    if (NPASS >= 2) srcs_[np_++] = (const char*)(Alo + (size_t)bm * K + k0_);    \
    srcs_[np_++] = (const char*)(Bhi + (size_t)bn * K + k0_);                    \
    if (NPASS == 3) srcs_[np_++] = (const char*)(Blo + (size_t)bn * K + k0_);    \
    _Pragma("unroll")                                                            \
    for (int p_ = 0; p_ < NPLANES; p_++) {                                       \
      char* dstp_ = smc + (s) * STGB + p_ * PLANE_B;                             \
      _Pragma("unroll")                                                          \
      for (int j_ = 0; j_ < 2; j_++) {                                           \
        int idx_ = j_ * 256 + tid;                                               \
        int row_ = idx_ >> 2, ch_ = idx_ & 3;                                    \
        unsigned sa_ = (unsigned)__cvta_generic_to_shared(dstp_ + row_ * LDPB + ch_ * 16); \
        const char* ga_ = srcs_[p_] + (size_t)row_ * K * 2 + ch_ * 16;           \
        asm volatile("cp.async.ca.shared.global [%0], [%1], 16;\n"               \
                     :: "r"(sa_), "l"(ga_));                                     \
      }                                                                          \
    }                                                                            \
    asm volatile("cp.async.commit_group;\n");                                    \
  } while (0)

  PREFETCH(0, 0);

  for (int kt = 0; kt < KT; kt++) {
    asm volatile("cp.async.wait_group 0;\n");
    __syncthreads();
    if (kt + 1 < KT) PREFETCH(kt + 1, (kt + 1) & 1);

    const char* Sahi = smc + (kt & 1) * STGB;
    const char* Salo = Sahi + PLANE_B;                         // NPASS>=2
    const char* Sbhi = Sahi + ((NPASS >= 2) ? 2 : 1) * PLANE_B;
    const char* Sblo = Sbhi + PLANE_B;                         // NPASS==3

    #pragma unroll
    for (int ks = 0; ks < 2; ks++) {
      int kb = ks * 32;   // 16 fp16 = 32 bytes
      unsigned bh_[2][4], bl_[2][4];
      #pragma unroll
      for (int pp = 0; pp < 2; pp++) {
        ldsm4(bh_[pp], Sbhi + (noff + pp * 16) * LDPB + kb + boff);
        if (NPASS == 3)
          ldsm4(bl_[pp], Sblo + (noff + pp * 16) * LDPB + kb + boff);
      }
      #pragma unroll
      for (int tm = 0; tm < 4; tm++) {
        unsigned ah[4], al[4];
        ldsm4(ah, Sahi + (moff + tm * 16) * LDPB + kb + aoff);
        if (NPASS >= 2)
          ldsm4(al, Salo + (moff + tm * 16) * LDPB + kb + aoff);
        #pragma unroll
        for (int tn = 0; tn < 4; tn++) {
          const unsigned* bhp = &bh_[tn >> 1][(tn & 1) * 2];
          mma_fp16(acc[tm][tn], ah, bhp);
          if (NPASS >= 2) mma_fp16(acc[tm][tn], al, bhp);
          if (NPASS == 3) {
            const unsigned* blp = &bl_[tn >> 1][(tn & 1) * 2];
            mma_fp16(acc[tm][tn], ah, blp);
          }
        }
      }
    }
    __syncthreads();
  }

  // ---- epilogue ----
  #pragma unroll
  for (int tm = 0; tm < 4; tm++) {
    int r0 = bm + moff + tm * 16 + g;
    int r1 = r0 + 8;
    #pragma unroll
    for (int tn = 0; tn < 4; tn++) {
      int c0 = bn + noff + tn * 8 + 2 * t4;   // even column
      float b0 = bias[c0], b1 = bias[c0 + 1];
      float v00 = acc[tm][tn][0] + b0;
      float v01 = acc[tm][tn][1] + b1;
      float v10 = acc[tm][tn][2] + b0;
      float v11 = acc[tm][tn][3] + b1;
      if (EPI == 1) {
        v00 = 0.5f * v00 * (1.f + erff(v00 * 0.70710678118654752f));
        v01 = 0.5f * v01 * (1.f + erff(v01 * 0.70710678118654752f));
        v10 = 0.5f * v10 * (1.f + erff(v10 * 0.70710678118654752f));
        v11 = 0.5f * v11 * (1.f + erff(v11 * 0.70710678118654752f));
        *(__half2*)(Chi + (size_t)r0 * N + c0) =
          __halves2half2(__float2half_rn(v00), __float2half_rn(v01));
        *(__half2*)(Chi + (size_t)r1 * N + c0) =
          __halves2half2(__float2half_rn(v10), __float2half_rn(v11));
      } else {
        if (EPI == 2) {
          float df = expf((float)c0 * (-0.017988946039015984f));
          float a0 = (float)(r0 & Lmask) * df;
          float a1 = (float)(r1 & Lmask) * df;
          v00 += sinf(a0); v01 += cosf(a0);
          v10 += sinf(a1); v11 += cosf(a1);
          *(__half2*)(Chh + (size_t)r0 * N + c0) =
            __halves2half2(__float2half_rn(v00), __float2half_rn(v01));
          *(__half2*)(Chh + (size_t)r1 * N + c0) =
            __halves2half2(__float2half_rn(v10), __float2half_rn(v11));
        }
        *(float2*)(Cf + (size_t)r0 * N + c0) = make_float2(v00, v01);
        *(float2*)(Cf + (size_t)r1 * N + c0) = make_float2(v10, v11);
      }
    }
  }
  #undef PREFETCH
}

// ------------------- host: layer key derivation ----------------------------
static void layer_key(int i, unsigned &k0, unsigned &k1)
{
  unsigned a = 0u, b = (unsigned)i;
  threefry2x32(0u, 42u, a, b);
  unsigned c = 0u, d = 1u;
  threefry2x32(a, b, c, d);
  k0 = c; k1 = d;
}

extern "C" void kernel_launch(void* const* d_in, const int* in_sizes, int n_in,
                              void* d_out, int out_size)
{
  const float* x     = (const float*)d_in[0];
  const float* emb_w = (const float*)d_in[1];
  const float* emb_b = (const float*)d_in[2];
  const float* ln1_s = (const float*)d_in[3];
  const float* ln1_b = (const float*)d_in[4];
  const float* w1    = (const float*)d_in[5];
  const float* b1    = (const float*)d_in[6];
  const float* w2    = (const float*)d_in[7];
  const float* b2    = (const float*)d_in[8];
  const float* ln2_s = (const float*)d_in[9];
  const float* ln2_b = (const float*)d_in[10];
  const float* out_w = (const float*)d_in[11];
  const float* out_b = (const float*)d_in[12];
  float* out = (float*)d_out;

  float *ph, *px, *pz;
  __half *phh, *pxhi, *pxlo, *pyhi;
  __half *pw1hi, *pw2hi, *powhi;
  __half *pexhi, *pexlo, *pewhi, *pewlo;
  cudaGetSymbolAddress((void**)&ph,   g_h);
  cudaGetSymbolAddress((void**)&phh,  g_hh);
  cudaGetSymbolAddress((void**)&px,   g_x);
  cudaGetSymbolAddress((void**)&pz,   g_z);
  cudaGetSymbolAddress((void**)&pxhi, g_xhi);
  cudaGetSymbolAddress((void**)&pxlo, g_xlo);
  cudaGetSymbolAddress((void**)&pyhi, g_yhi);
  cudaGetSymbolAddress((void**)&pw1hi, g_w1hi);
  cudaGetSymbolAddress((void**)&pw2hi, g_w2hi);
  cudaGetSymbolAddress((void**)&powhi, g_owhi);
  cudaGetSymbolAddress((void**)&pexhi, g_exhi);
  cudaGetSymbolAddress((void**)&pexlo, g_exlo);
  cudaGetSymbolAddress((void**)&pewhi, g_ewhi);
  cudaGetSymbolAddress((void**)&pewlo, g_ewlo);

  static int smem_set = 0;
  if (!smem_set) {
    cudaFuncSetAttribute(mma_gemm<2,3>, cudaFuncAttributeMaxDynamicSharedMemorySize, 2 * 4 * PLANE_B);
    cudaFuncSetAttribute(mma_gemm<1,1>, cudaFuncAttributeMaxDynamicSharedMemorySize, 2 * 2 * PLANE_B);
    cudaFuncSetAttribute(mma_gemm<0,1>, cudaFuncAttributeMaxDynamicSharedMemorySize, 2 * 2 * PLANE_B);
    cudaFuncSetAttribute(mma_gemm<0,2>, cudaFuncAttributeMaxDynamicSharedMemorySize, 2 * 3 * PLANE_B);
    cudaFuncSetAttribute(ctx_split_kernel, cudaFuncAttributeMaxDynamicSharedMemorySize, CTX_SMEM_FLOATS * 4);
    smem_set = 1;
  }
  const int ctx_smem = CTX_SMEM_FLOATS * 4;

  // input conversions (embed deps)
  {
    int n3 = BB * L0 * 64;
    xsplit_kernel<<<(n3 + 255) / 256, 256>>>(x, pexhi, pexlo, n3);
    int n4 = DD * 64;
    xsplit_kernel<<<(n4 + 255) / 256, 256>>>(emb_w, pewhi, pewlo, n4);
  }

  // Embed (3-pass fp16 mma): h = x @ emb_w^T + emb_b + PE; also fp16 mirror
  {
    int M = BB * L0;
    mma_gemm<2,3><<<dim3(DD / 128, M / 128), 256, 2 * 4 * PLANE_B>>>(
        pexhi, pexlo, pewhi, pewlo, emb_b, ph, nullptr, phh, M, DD, 64, L0 - 1);
  }

  int L = L0;
  float* cur = ph;
  for (int i = 0; i < 3; i++) {
    int u = (i == 0) ? 45 : (i == 1) ? 40 : 35;
    int M = BB * L;
    unsigned k0, k1; layer_key(i, k0, k1);
    prob_m_kernel<<<dim3(L / 8, 64), 256>>>(phh, L, u, 1.0f / (float)L,
                                            k0, k1, L - 1);
    topk_kernel<<<64, 256>>>(L, u);
    int nsplit = L / 512; if (nsplit < 1) nsplit = 1; if (nsplit > 8) nsplit = 8;
    ctx_split_kernel<<<dim3(nsplit, 64), 256, ctx_smem>>>(phh, L, u, L / nsplit);
    ctx_merge_kernel<<<64, 256>>>(L, u, nsplit);
    assemble_ln1_kernel<<<M, 128>>>(cur, px, pxhi,
                                    ln1_s + i * DD, ln1_b + i * DD, L, u);

    if (i == 0) {
      int n1 = 3 * DFF * DD;
      whalf_kernel<<<(n1 + 255) / 256, 256>>>(w1, pw1hi, n1);
      whalf_kernel<<<(n1 + 255) / 256, 256>>>(w2, pw2hi, n1);
      int n2 = DD * DD;
      whalf_kernel<<<(n2 + 255) / 256, 256>>>(out_w, powhi, n2);
    }

    // FFN1: y = gelu(x @ w1^T + b1), 1-pass, fp16 out
    mma_gemm<1,1><<<dim3(DFF / 128, M / 128), 256, 2 * 2 * PLANE_B>>>(
        pxhi, nullptr, pw1hi + (size_t)i * DFF * DD, nullptr,
        b1 + i * DFF, nullptr, pyhi, nullptr, M, DFF, DD, 0);
    // FFN2: z = y @ w2^T + b2, 1-pass, fp32 out
    mma_gemm<0,1><<<dim3(DD / 128, M / 128), 256, 2 * 2 * PLANE_B>>>(
        pyhi, nullptr, pw2hi + (size_t)i * DD * DFF, nullptr,
        b2 + i * DD, pz, nullptr, nullptr, M, DD, DFF, 0);

    if (i < 2) {
      int L2 = L / 2;
      ln2_distil_kernel<<<BB * L2, 128>>>(px, pz, cur, phh,
                                          ln2_s + i * DD, ln2_b + i * DD, L2);
      L = L2;
    } else {
      ln2_split_kernel<<<M, 128>>>(px, pz, pxhi, pxlo,
                                   ln2_s + i * DD, ln2_b + i * DD);
    }
  }

  // Final projection: out = h @ out_w^T + out_b, 2-pass A (M=8192,N=512,K=512)
  {
    int M = BB * L;   // L = 1024
    mma_gemm<0,2><<<dim3(DD / 128, M / 128), 256, 2 * 3 * PLANE_B>>>(
        pxhi, pxlo, powhi, nullptr, out_b, out, nullptr, nullptr, M, DD, DD, 0);
  }
}

// round 17
// speedup vs baseline: 1.0060x; 1.0060x over previous
#include <cuda_runtime.h>
#include <cuda_fp16.h>
#include <math.h>
#include <stdint.h>

#define BB 8
#define DD 512
#define DFF 2048
#define L0 4096
#define UMAX 45
#define LN_EPS 1e-5f

// ------------------- scratch (device globals; no allocs) -------------------
__device__ __align__(16) float g_h  [BB*L0*DD];
__device__ __align__(16) __half g_hh [BB*L0*DD];   // fp16 mirror for attention reads
__device__ __align__(16) float g_x  [BB*L0*DD];
__device__ __align__(16) float g_z  [BB*L0*DD];
__device__ __align__(16) __half g_xhi[BB*L0*DD];
__device__ __align__(16) __half g_xlo[BB*L0*DD];
__device__ __align__(16) __half g_yhi[BB*L0*DFF];
__device__ __align__(16) __half g_w1hi[3*DFF*DD];
__device__ __align__(16) __half g_w2hi[3*DD*DFF];
__device__ __align__(16) __half g_owhi[DD*DD];
__device__ __align__(16) __half g_exhi[BB*L0*64];
__device__ __align__(16) __half g_exlo[BB*L0*64];
__device__ __align__(16) __half g_ewhi[DD*64];
__device__ __align__(16) __half g_ewlo[DD*64];
__device__ __align__(16) float g_M  [BB*8*L0];
__device__ __align__(16) int   g_top[BB*8*UMAX];
__device__ __align__(16) int   g_rowmap[BB*8*L0];
__device__ __align__(16) float g_ctx[BB*8*UMAX*64];
__device__ __align__(16) float g_qmean[BB*8*64];
// split-L ctx partials (max 8 splits)
__device__ __align__(16) float g_pm  [64*8*UMAX];
__device__ __align__(16) float g_ps  [64*8*UMAX];
__device__ __align__(16) float g_pctx[64*8*UMAX*64];
__device__ __align__(16) float g_pq  [64*8*64];

// ------------------- fp16 split helpers -------------------------------------
__device__ __forceinline__ void split_fp16(float v, __half &hi, __half &lo)
{
  hi = __float2half_rn(v);
  lo = __float2half_rn(v - __half2float(hi));
}

// ------------------- threefry2x32 (JAX-compatible) -------------------------
#define TF_R(x0,x1,r) { x0 += x1; x1 = ((x1 << (r)) | (x1 >> (32-(r)))); x1 ^= x0; }
__host__ __device__ __forceinline__ void threefry2x32(unsigned ks0, unsigned ks1,
                                                      unsigned &x0, unsigned &x1)
{
  unsigned ks2 = ks0 ^ ks1 ^ 0x1BD11BDAu;
  x0 += ks0; x1 += ks1;
  TF_R(x0,x1,13) TF_R(x0,x1,15) TF_R(x0,x1,26) TF_R(x0,x1,6)
  x0 += ks1; x1 += ks2 + 1u;
  TF_R(x0,x1,17) TF_R(x0,x1,29) TF_R(x0,x1,16) TF_R(x0,x1,24)
  x0 += ks2; x1 += ks0 + 2u;
  TF_R(x0,x1,13) TF_R(x0,x1,15) TF_R(x0,x1,26) TF_R(x0,x1,6)
  x0 += ks0; x1 += ks1 + 3u;
  TF_R(x0,x1,17) TF_R(x0,x1,29) TF_R(x0,x1,16) TF_R(x0,x1,24)
  x0 += ks1; x1 += ks2 + 4u;
  TF_R(x0,x1,13) TF_R(x0,x1,15) TF_R(x0,x1,26) TF_R(x0,x1,6)
  x0 += ks2; x1 += ks0 + 5u;
}

// ------------------- splits -------------------------------------------------
__global__ void whalf_kernel(const float* __restrict__ w,
                             __half* __restrict__ hi, int n)
{
  int i = blockIdx.x * 256 + threadIdx.x;
  if (i >= n) return;
  hi[i] = __float2half_rn(w[i]);
}

__global__ void xsplit_kernel(const float* __restrict__ w,
                              __half* __restrict__ hi, __half* __restrict__ lo, int n)
{
  int i = blockIdx.x * 256 + threadIdx.x;
  if (i >= n) return;
  __half h, l;
  split_fp16(w[i], h, l);
  hi[i] = h; lo[i] = l;
}

// ------------------- M = max_s qk - sum_s qk / L ----------------------------
// quarter-warp scheme (R15 structure): each 8-lane quarter computes a FULL
// 64-dim dot for its own sample; indices pre-scaled to BYTE offsets so the
// per-sample address math is a single add.
__device__ __forceinline__ float dot8(const float* qv, uint4 t)
{
  const __half2* hp = (const __half2*)&t;
  float2 f0 = __half22float2(hp[0]);
  float2 f1 = __half22float2(hp[1]);
  float2 f2 = __half22float2(hp[2]);
  float2 f3 = __half22float2(hp[3]);
  return qv[0]*f0.x + qv[1]*f0.y + qv[2]*f1.x + qv[3]*f1.y
       + qv[4]*f2.x + qv[5]*f2.y + qv[6]*f3.x + qv[7]*f3.y;
}

__global__ __launch_bounds__(256) void prob_m_kernel(
    const __half* __restrict__ hh, int L, int u, float invL,
    unsigned k0, unsigned k1, int mask)
{
  int bh = blockIdx.y; int b = bh >> 3, hd = bh & 7;
  int warp = threadIdx.x >> 5, lane = threadIdx.x & 31;
  int l = blockIdx.x * 8 + warp;
  const __half* base = hh + (size_t)b * L * DD + hd * 64;
  const int lane8 = lane & 7;
  const int quad  = lane >> 3;
  const char* base8 = (const char*)(base + lane8 * 8);   // per-lane column ptr

  float qv[8];
  {
    uint4 t = *(const uint4*)(base8 + (size_t)l * (DD * 2));
    const __half2* hp = (const __half2*)&t;
    float2 f0 = __half22float2(hp[0]);
    float2 f1 = __half22float2(hp[1]);
    float2 f2 = __half22float2(hp[2]);
    float2 f3 = __half22float2(hp[3]);
    qv[0]=f0.x; qv[1]=f0.y; qv[2]=f1.x; qv[3]=f1.y;
    qv[4]=f2.x; qv[5]=f2.y; qv[6]=f3.x; qv[7]=f3.y;
  }

  // inline threefry (partitionable): bits[t] = y0^y1 of TF(k2,(0,t)), t=l*u+s
  // store BYTE offsets (idx * DD * 2; max 4MB fits int32)
  int offA = 0, offB = 0;
  {
    unsigned x0 = 0u, x1 = (unsigned)(l * u + lane);
    threefry2x32(k0, k1, x0, x1);
    if (lane < u) offA = (int)((x0 ^ x1) & (unsigned)mask) * (DD * 2);
    unsigned y0 = 0u, y1 = (unsigned)(l * u + lane + 32);
    threefry2x32(k0, k1, y0, y1);
    if (lane + 32 < u) offB = (int)((y0 ^ y1) & (unsigned)mask) * (DD * 2);
  }

  float mx = -INFINITY, sm = 0.f;
  int s = 0;
  // 4 samples per iteration: quarter q handles sample s+q
  for (; s + 3 < u; s += 4) {
    int sq = s + quad;
    int off = __shfl_sync(0xffffffffu, (s < 32) ? offA : offB, sq & 31);
    uint4 t = *(const uint4*)(base8 + off);
    float p = dot8(qv, t);
    #pragma unroll
    for (int o = 4; o; o >>= 1) p += __shfl_xor_sync(0xffffffffu, p, o);
    mx = fmaxf(mx, p); sm += p;
  }
  // tail: all quarters compute the same sample; quarter 0 accumulates
  for (; s < u; s++) {
    int off = __shfl_sync(0xffffffffu, (s < 32) ? offA : offB, s & 31);
    uint4 t = *(const uint4*)(base8 + off);
    float p = dot8(qv, t);
    #pragma unroll
    for (int o = 4; o; o >>= 1) p += __shfl_xor_sync(0xffffffffu, p, o);
    if (quad == 0) { mx = fmaxf(mx, p); sm += p; }
  }
  // merge quarters
  #pragma unroll
  for (int o = 8; o <= 16; o <<= 1) {
    mx = fmaxf(mx, __shfl_xor_sync(0xffffffffu, mx, o));
    sm += __shfl_xor_sync(0xffffffffu, sm, o);
  }
  if (lane == 0) g_M[(size_t)bh * L + l] = mx - sm * invL;
}

// ------------------- top-k: tournament argmax (exact, lower-index ties) ----
__global__ __launch_bounds__(256) void topk_kernel(int L, int u)
{
  __shared__ float sM[L0];
  __shared__ float gmax[64];
  __shared__ int   gidx[64];
  int bh = blockIdx.x;
  int tid = threadIdx.x;
  int ngroups = L >> 6;
  for (int l = tid; l < L; l += 256) {
    sM[l] = g_M[(size_t)bh * L + l];
    g_rowmap[(size_t)bh * L + l] = -1;
  }
  __syncthreads();
  if (tid < ngroups) {
    float bv = -INFINITY; int bi = tid * 64;
    #pragma unroll 8
    for (int j = 0; j < 64; j++) {
      float v = sM[tid * 64 + j];
      if (v > bv) { bv = v; bi = tid * 64 + j; }
    }
    gmax[tid] = bv; gidx[tid] = bi;
  }
  __syncthreads();

  if (tid < 32) {
    for (int r = 0; r < u; r++) {
      float bv = -INFINITY; int bi = 0x7fffffff;
      for (int g = tid; g < ngroups; g += 32) {
        float v = gmax[g]; int i = gidx[g];
        if (v > bv || (v == bv && i < bi)) { bv = v; bi = i; }
      }
      #pragma unroll
      for (int o = 16; o; o >>= 1) {
        float v2 = __shfl_xor_sync(0xffffffffu, bv, o);
        int   i2 = __shfl_xor_sync(0xffffffffu, bi, o);
        if (v2 > bv || (v2 == bv && i2 < bi)) { bv = v2; bi = i2; }
      }
      int sel = __shfl_sync(0xffffffffu, bi, 0);
      if (tid == 0) {
        g_top[bh * u + r] = sel;
        g_rowmap[(size_t)bh * L + sel] = r;
        sM[sel] = -INFINITY;
      }
      __syncwarp();
      int gs = sel >> 6;
      int e0 = gs * 64 + tid, e1 = e0 + 32;
      float v0 = sM[e0], v1 = sM[e1];
      float nv; int ni;
      if (v0 >= v1) { nv = v0; ni = e0; } else { nv = v1; ni = e1; }
      if (v0 == v1) { ni = e0; }
      #pragma unroll
      for (int o = 16; o; o >>= 1) {
        float v2 = __shfl_xor_sync(0xffffffffu, nv, o);
        int   i2 = __shfl_xor_sync(0xffffffffu, ni, o);
        if (v2 > nv || (v2 == nv && i2 < ni)) { nv = v2; ni = i2; }
      }
      if (tid == 0) { gmax[gs] = nv; gidx[gs] = ni; }
      __syncwarp();
    }
  }
}

// ------------------- split-L ctx (fp16 key reads; R12 strided form) ---------
// smem floats: qs 3072 | kt 4352 | sc 3072 | ctxs 3072 | rm/rs/rsc 144 | qred 256
#define CTX_SMEM_FLOATS (13568 + 144 + 256)
__global__ __launch_bounds__(256) void ctx_split_kernel(
    const __half* __restrict__ hh, int L, int u, int klen)
{
  extern __shared__ float dsm[];
  float* qs   = dsm;            // stride 64
  float* kt   = dsm + 3072;     // stride 68
  float* sc   = dsm + 7424;     // stride 64
  float* ctxs = dsm + 10496;    // stride 64
  float* rm   = dsm + 13568;
  float* rs   = dsm + 13616;
  float* rsc  = dsm + 13664;
  float* qred = dsm + 13712;    // [4][64]

  int split = blockIdx.x;
  int bh = blockIdx.y; int b = bh >> 3, hd = bh & 7;
  const __half* base = hh + (size_t)b * L * DD + hd * 64;
  int tid = threadIdx.x;
  int kbeg = split * klen;

  for (int e = tid; e < u * 64; e += 256) {
    int r = e >> 6, d = e & 63;
    qs[r * 64 + d] = __half2float(base[(size_t)g_top[bh * u + r] * DD + d]);
    ctxs[e] = 0.f;
  }
  if (tid < u) { rm[tid] = -INFINITY; rs[tid] = 0.f; }
  __syncthreads();

  const int j  = tid & 63;
  const int rg = tid >> 6;
  const int w  = tid >> 5, lane = tid & 31;
  float qacc = 0.f;

  for (int t0 = kbeg; t0 < kbeg + klen; t0 += 64) {
    for (int e = tid; e < 64 * 8; e += 256) {
      int r = e >> 3, c8 = e & 7;
      uint4 v = *(const uint4*)(base + (size_t)(t0 + r) * DD + c8 * 8);
      const __half2* hp = (const __half2*)&v;
      float* kr = kt + r * 68 + c8 * 8;
      #pragma unroll
      for (int q = 0; q < 4; q++) {
        float2 f = __half22float2(hp[q]);
        kr[2 * q] = f.x; kr[2 * q + 1] = f.y;
      }
    }
    __syncthreads();

    #pragma unroll
    for (int r = 0; r < 16; r++) qacc += kt[(rg + r * 4) * 68 + j];

    {
      float kreg[64];
      #pragma unroll
      for (int d = 0; d < 64; d++) kreg[d] = kt[j * 68 + d];
      for (int r = rg; r < u; r += 4) {
        const float* qr = qs + r * 64;
        float dot = 0.f;
        #pragma unroll
        for (int d = 0; d < 64; d++) dot += qr[d] * kreg[d];
        sc[r * 64 + j] = dot * 0.125f;
      }
    }
    __syncthreads();
    for (int r = w; r < u; r += 8) {
      float v0 = sc[r * 64 + lane], v1 = sc[r * 64 + lane + 32];
      float mx = fmaxf(v0, v1);
      #pragma unroll
      for (int o = 16; o; o >>= 1) mx = fmaxf(mx, __shfl_xor_sync(0xffffffffu, mx, o));
      float mold = rm[r];
      float mnew = fmaxf(mold, mx);
      float p0 = __expf(v0 - mnew), p1 = __expf(v1 - mnew);
      float ps = p0 + p1;
      #pragma unroll
      for (int o = 16; o; o >>= 1) ps += __shfl_xor_sync(0xffffffffu, ps, o);
      if (lane == 0) {
        float cold = __expf(mold - mnew);
        rsc[r] = cold;
        rs[r] = rs[r] * cold + ps;
        rm[r] = mnew;
      }
      sc[r * 64 + lane] = p0; sc[r * 64 + lane + 32] = p1;
    }
    __syncthreads();
    for (int r = rg; r < u; r += 4) {
      const float* pr = sc + r * 64;
      float a = 0.f;
      #pragma unroll
      for (int jj = 0; jj < 64; jj++) a += pr[jj] * kt[jj * 68 + j];
      ctxs[r * 64 + j] = ctxs[r * 64 + j] * rsc[r] + a;
    }
    __syncthreads();
  }

  // write partials
  qred[rg * 64 + j] = qacc;
  __syncthreads();
  if (rg == 0)
    g_pq[(bh * 8 + split) * 64 + j] =
      qred[j] + qred[64 + j] + qred[128 + j] + qred[192 + j];
  if (tid < u) {
    g_pm[(bh * 8 + split) * UMAX + tid] = rm[tid];
    g_ps[(bh * 8 + split) * UMAX + tid] = rs[tid];
  }
  for (int e = tid; e < u * 64; e += 256) {
    int r = e >> 6, d = e & 63;
    g_pctx[((size_t)((bh * 8 + split) * UMAX + r)) * 64 + d] = ctxs[r * 64 + d];
  }
}

// ------------------- merge split-L partials ---------------------------------
__global__ __launch_bounds__(256) void ctx_merge_kernel(int L, int u, int nsplit)
{
  int bh = blockIdx.x;
  int tid = threadIdx.x;
  if (tid < 64) {
    float q = 0.f;
    for (int s = 0; s < nsplit; s++) q += g_pq[(bh * 8 + s) * 64 + tid];
    g_qmean[bh * 64 + tid] = q / (float)L;
  }
  for (int e = tid; e < u * 64; e += 256) {
    int r = e >> 6, d = e & 63;
    float M0 = -INFINITY;
    for (int s = 0; s < nsplit; s++)
      M0 = fmaxf(M0, g_pm[(bh * 8 + s) * UMAX + r]);
    float num = 0.f, den = 0.f;
    for (int s = 0; s < nsplit; s++) {
      float c = __expf(g_pm[(bh * 8 + s) * UMAX + r] - M0);
      num += g_pctx[((size_t)((bh * 8 + s) * UMAX + r)) * 64 + d] * c;
      den += g_ps[(bh * 8 + s) * UMAX + r] * c;
    }
    g_ctx[((size_t)(bh * u + r)) * 64 + d] = num / den;
  }
}

// ------------------- block reduce helper (128 threads) ---------------------
__device__ __forceinline__ float blocksum128(float v, float* sred)
{
  #pragma unroll
  for (int o = 16; o; o >>= 1) v += __shfl_xor_sync(0xffffffffu, v, o);
  if ((threadIdx.x & 31) == 0) sred[threadIdx.x >> 5] = v;
  __syncthreads();
  float t = sred[0] + sred[1] + sred[2] + sred[3];
  __syncthreads();
  return t;
}

// ------------------- assemble attention out + residual + LN1 + fp16 hi -----
__global__ __launch_bounds__(128) void assemble_ln1_kernel(
    const float* __restrict__ hin, float* __restrict__ xout,
    __half* __restrict__ xhi,
    const float* __restrict__ gamma, const float* __restrict__ beta,
    int L, int u)
{
  __shared__ float sred[4];
  int row = blockIdx.x;
  int b = row / L, l = row - b * L;
  int tid = threadIdx.x;
  float v[4];
  #pragma unroll
  for (int i = 0; i < 4; i++) {
    int e = i * 128 + tid;
    int hh = e >> 6, dd = e & 63;
    int bh = b * 8 + hh;
    int r = g_rowmap[(size_t)bh * L + l];
    float nv = (r >= 0) ? g_ctx[((size_t)(bh * u + r)) * 64 + dd]
                        : g_qmean[bh * 64 + dd];
    v[i] = hin[(size_t)row * DD + e] + nv;
  }
  float s = blocksum128(v[0] + v[1] + v[2] + v[3], sred);
  float mu = s * (1.0f / 512.0f);
  float vs = 0.f;
  #pragma unroll
  for (int i = 0; i < 4; i++) { float d = v[i] - mu; vs += d * d; }
  vs = blocksum128(vs, sred);
  float rstd = rsqrtf(vs * (1.0f / 512.0f) + LN_EPS);
  #pragma unroll
  for (int i = 0; i < 4; i++) {
    int e = i * 128 + tid;
    float o = (v[i] - mu) * rstd * gamma[e] + beta[e];
    xout[(size_t)row * DD + e] = o;
    xhi[(size_t)row * DD + e] = __float2half_rn(o);
  }
}

// ------------------- fused residual+LN2+distil (layers 0,1) ----------------
__global__ __launch_bounds__(128) void ln2_distil_kernel(
    const float* __restrict__ xin, const float* __restrict__ zin,
    float* __restrict__ outp, __half* __restrict__ outh,
    const float* __restrict__ gamma, const float* __restrict__ beta, int L2)
{
  __shared__ float sred[4];
  int rowo = blockIdx.x;
  int b = rowo / L2, l2 = rowo - b * L2;
  size_t r0 = ((size_t)b * (2 * L2) + 2 * l2);
  int tid = threadIdx.x;
  float o01[4];
  #pragma unroll
  for (int half = 0; half < 2; half++) {
    size_t row = r0 + half;
    float v[4];
    #pragma unroll
    for (int i = 0; i < 4; i++) {
      int e = i * 128 + tid;
      v[i] = xin[row * DD + e] + zin[row * DD + e];
    }
    float s = blocksum128(v[0] + v[1] + v[2] + v[3], sred);
    float mu = s * (1.0f / 512.0f);
    float vs = 0.f;
    #pragma unroll
    for (int i = 0; i < 4; i++) { float d = v[i] - mu; vs += d * d; }
    vs = blocksum128(vs, sred);
    float rstd = rsqrtf(vs * (1.0f / 512.0f) + LN_EPS);
    #pragma unroll
    for (int i = 0; i < 4; i++) {
      int e = i * 128 + tid;
      float o = (v[i] - mu) * rstd * gamma[e] + beta[e];
      if (half == 0) o01[i] = o; else o01[i] = 0.5f * (o01[i] + o);
    }
  }
  #pragma unroll
  for (int i = 0; i < 4; i++) {
    int e = i * 128 + tid;
    outp[(size_t)rowo * DD + e] = o01[i];
    outh[(size_t)rowo * DD + e] = __float2half_rn(o01[i]);
  }
}

// ------------------- residual + LN2 -> fp16 split only (last layer) --------
__global__ __launch_bounds__(128) void ln2_split_kernel(
    const float* __restrict__ xin, const float* __restrict__ zin,
    __half* __restrict__ ohi, __half* __restrict__ olo,
    const float* __restrict__ gamma, const float* __restrict__ beta)
{
  __shared__ float sred[4];
  size_t row = blockIdx.x;
  int tid = threadIdx.x;
  float v[4];
  #pragma unroll
  for (int i = 0; i < 4; i++) {
    int e = i * 128 + tid;
    v[i] = xin[row * DD + e] + zin[row * DD + e];
  }
  float s = blocksum128(v[0] + v[1] + v[2] + v[3], sred);
  float mu = s * (1.0f / 512.0f);
  float vs = 0.f;
  #pragma unroll
  for (int i = 0; i < 4; i++) { float d = v[i] - mu; vs += d * d; }
  vs = blocksum128(vs, sred);
  float rstd = rsqrtf(vs * (1.0f / 512.0f) + LN_EPS);
  #pragma unroll
  for (int i = 0; i < 4; i++) {
    int e = i * 128 + tid;
    float o = (v[i] - mu) * rstd * gamma[e] + beta[e];
    __half h16, l16;
    split_fp16(o, h16, l16);
    ohi[row * DD + e] = h16;
    olo[row * DD + e] = l16;
  }
}

// ------------------- fp16 tensor-core GEMM (1/2/3-pass) ---------------------
#define KC 32                     // k elems per stage
#define LDPB 80                   // padded row stride in BYTES (40 fp16)
#define PLANE_B (128*LDPB)        // 10240 bytes per plane

__device__ __forceinline__ void mma_fp16(float* c, const unsigned* a, const unsigned* b)
{
  asm volatile(
    "mma.sync.aligned.m16n8k16.row.col.f32.f16.f16.f32 "
    "{%0,%1,%2,%3},{%4,%5,%6,%7},{%8,%9},{%0,%1,%2,%3};\n"
    : "+f"(c[0]), "+f"(c[1]), "+f"(c[2]), "+f"(c[3])
    : "r"(a[0]), "r"(a[1]), "r"(a[2]), "r"(a[3]), "r"(b[0]), "r"(b[1]));
}

__device__ __forceinline__ void ldsm4(unsigned* r, const char* sptr)
{
  unsigned addr = (unsigned)__cvta_generic_to_shared(sptr);
  asm volatile("ldmatrix.sync.aligned.m8n8.x4.shared.b16 {%0,%1,%2,%3}, [%4];\n"
    : "=r"(r[0]), "=r"(r[1]), "=r"(r[2]), "=r"(r[3]) : "r"(addr));
}

// EPI 0: Cf = acc + bias (fp32)
// EPI 1: Chi = fp16(gelu(acc + bias))
// EPI 2: Cf = acc + bias + PE (fp32) AND Chh = fp16 copy
// NPASS 1: A_hi x B_hi | NPASS 2: (A_hi+A_lo) x B_hi | NPASS 3: + A_hi x B_lo
template<int EPI, int NPASS>
__global__ __launch_bounds__(256, 2) void mma_gemm(
    const __half* __restrict__ Ahi, const __half* __restrict__ Alo,
    const __half* __restrict__ Bhi, const __half* __restrict__ Blo,
    const float* __restrict__ bias,
    float* __restrict__ Cf, __half* __restrict__ Chi, __half* __restrict__ Chh,
    int M, int N, int K, int Lmask)
{
  constexpr int NPLANES = (NPASS == 3) ? 4 : (NPASS + 1);
  const int STGB = NPLANES * PLANE_B;
  extern __shared__ char smc[];
  const int tid = threadIdx.x;
  const int bm = blockIdx.y * 128, bn = blockIdx.x * 128;
  const int lane = tid & 31;
  const int g = lane >> 2, t4 = lane & 3;
  const int warp = tid >> 5;
  const int wm = warp >> 2, wn = warp & 3;      // warps 2(m) x 4(n)
  const int moff = wm * 64, noff = wn * 32;

  const int aoff = (lane & 15) * LDPB + ((lane & 16) ? 16 : 0);
  const int boff = ((lane & 7) + ((lane & 16) ? 8 : 0)) * LDPB + ((lane & 8) ? 16 : 0);

  float acc[4][4][4];
  #pragma unroll
  for (int i = 0; i < 4; i++)
    #pragma unroll
    for (int j = 0; j < 4; j++)
      #pragma unroll
      for (int q = 0; q < 4; q++) acc[i][j][q] = 0.f;

  const int KT = K / KC;

  #define PREFETCH(kt, s) do {                                                   \
    int k0_ = (kt) * KC;                                                         \
    const char* srcs_[NPLANES];                                                  \
    int np_ = 0;                                                                 \
    srcs_[np_++] = (const char*)(Ahi + (size_t)bm * K + k0_);                    \
    if (NPASS >= 2) srcs_[np_++] = (const char*)(Alo + (size_t)bm * K + k0_);    \
    srcs_[np_++] = (const char*)(Bhi + (size_t)bn * K + k0_);                    \
    if (NPASS == 3) srcs_[np_++] = (const char*)(Blo + (size_t)bn * K + k0_);    \
    _Pragma("unroll")                                                            \
    for (int p_ = 0; p_ < NPLANES; p_++) {                                       \
      char* dstp_ = smc + (s) * STGB + p_ * PLANE_B;                             \
      _Pragma("unroll")                                                          \
      for (int j_ = 0; j_ < 2; j_++) {                                           \
        int idx_ = j_ * 256 + tid;                                               \
        int row_ = idx_ >> 2, ch_ = idx_ & 3;                                    \
        unsigned sa_ = (unsigned)__cvta_generic_to_shared(dstp_ + row_ * LDPB + ch_ * 16); \
        const char* ga_ = srcs_[p_] + (size_t)row_ * K * 2 + ch_ * 16;           \
        asm volatile("cp.async.ca.shared.global [%0], [%1], 16;\n"               \
                     :: "r"(sa_), "l"(ga_));                                     \
      }                                                                          \
    }                                                                            \
    asm volatile("cp.async.commit_group;\n");                                    \
  } while (0)

  PREFETCH(0, 0);

  for (int kt = 0; kt < KT; kt++) {
    asm volatile("cp.async.wait_group 0;\n");
    __syncthreads();
    if (kt + 1 < KT) PREFETCH(kt + 1, (kt + 1) & 1);

    const char* Sahi = smc + (kt & 1) * STGB;
    const char* Salo = Sahi + PLANE_B;                         // NPASS>=2
    const char* Sbhi = Sahi + ((NPASS >= 2) ? 2 : 1) * PLANE_B;
    const char* Sblo = Sbhi + PLANE_B;                         // NPASS==3

    #pragma unroll
    for (int ks = 0; ks < 2; ks++) {
      int kb = ks * 32;   // 16 fp16 = 32 bytes
      unsigned bh_[2][4], bl_[2][4];
      #pragma unroll
      for (int pp = 0; pp < 2; pp++) {
        ldsm4(bh_[pp], Sbhi + (noff + pp * 16) * LDPB + kb + boff);
        if (NPASS == 3)
          ldsm4(bl_[pp], Sblo + (noff + pp * 16) * LDPB + kb + boff);
      }
      #pragma unroll
      for (int tm = 0; tm < 4; tm++) {
        unsigned ah[4], al[4];
        ldsm4(ah, Sahi + (moff + tm * 16) * LDPB + kb + aoff);
        if (NPASS >= 2)
          ldsm4(al, Salo + (moff + tm * 16) * LDPB + kb + aoff);
        #pragma unroll
        for (int tn = 0; tn < 4; tn++) {
          const unsigned* bhp = &bh_[tn >> 1][(tn & 1) * 2];
          mma_fp16(acc[tm][tn], ah, bhp);
          if (NPASS >= 2) mma_fp16(acc[tm][tn], al, bhp);
          if (NPASS == 3) {
            const unsigned* blp = &bl_[tn >> 1][(tn & 1) * 2];
            mma_fp16(acc[tm][tn], ah, blp);
          }
        }
      }
    }
    __syncthreads();
  }

  // ---- epilogue ----
  #pragma unroll
  for (int tm = 0; tm < 4; tm++) {
    int r0 = bm + moff + tm * 16 + g;
    int r1 = r0 + 8;
    #pragma unroll
    for (int tn = 0; tn < 4; tn++) {
      int c0 = bn + noff + tn * 8 + 2 * t4;   // even column
      float b0 = bias[c0], b1 = bias[c0 + 1];
      float v00 = acc[tm][tn][0] + b0;
      float v01 = acc[tm][tn][1] + b1;
      float v10 = acc[tm][tn][2] + b0;
      float v11 = acc[tm][tn][3] + b1;
      if (EPI == 1) {
        v00 = 0.5f * v00 * (1.f + erff(v00 * 0.70710678118654752f));
        v01 = 0.5f * v01 * (1.f + erff(v01 * 0.70710678118654752f));
        v10 = 0.5f * v10 * (1.f + erff(v10 * 0.70710678118654752f));
        v11 = 0.5f * v11 * (1.f + erff(v11 * 0.70710678118654752f));
        *(__half2*)(Chi + (size_t)r0 * N + c0) =
          __halves2half2(__float2half_rn(v00), __float2half_rn(v01));
        *(__half2*)(Chi + (size_t)r1 * N + c0) =
          __halves2half2(__float2half_rn(v10), __float2half_rn(v11));
      } else {
        if (EPI == 2) {
          float df = expf((float)c0 * (-0.017988946039015984f));
          float a0 = (float)(r0 & Lmask) * df;
          float a1 = (float)(r1 & Lmask) * df;
          v00 += sinf(a0); v01 += cosf(a0);
          v10 += sinf(a1); v11 += cosf(a1);
          *(__half2*)(Chh + (size_t)r0 * N + c0) =
            __halves2half2(__float2half_rn(v00), __float2half_rn(v01));
          *(__half2*)(Chh + (size_t)r1 * N + c0) =
            __halves2half2(__float2half_rn(v10), __float2half_rn(v11));
        }
        *(float2*)(Cf + (size_t)r0 * N + c0) = make_float2(v00, v01);
        *(float2*)(Cf + (size_t)r1 * N + c0) = make_float2(v10, v11);
      }
    }
  }
  #undef PREFETCH
}

// ------------------- host: layer key derivation ----------------------------
static void layer_key(int i, unsigned &k0, unsigned &k1)
{
  unsigned a = 0u, b = (unsigned)i;
  threefry2x32(0u, 42u, a, b);
  unsigned c = 0u, d = 1u;
  threefry2x32(a, b, c, d);
  k0 = c; k1 = d;
}

extern "C" void kernel_launch(void* const* d_in, const int* in_sizes, int n_in,
                              void* d_out, int out_size)
{
  const float* x     = (const float*)d_in[0];
  const float* emb_w = (const float*)d_in[1];
  const float* emb_b = (const float*)d_in[2];
  const float* ln1_s = (const float*)d_in[3];
  const float* ln1_b = (const float*)d_in[4];
  const float* w1    = (const float*)d_in[5];
  const float* b1    = (const float*)d_in[6];
  const float* w2    = (const float*)d_in[7];
  const float* b2    = (const float*)d_in[8];
  const float* ln2_s = (const float*)d_in[9];
  const float* ln2_b = (const float*)d_in[10];
  const float* out_w = (const float*)d_in[11];
  const float* out_b = (const float*)d_in[12];
  float* out = (float*)d_out;

  float *ph, *px, *pz;
  __half *phh, *pxhi, *pxlo, *pyhi;
  __half *pw1hi, *pw2hi, *powhi;
  __half *pexhi, *pexlo, *pewhi, *pewlo;
  cudaGetSymbolAddress((void**)&ph,   g_h);
  cudaGetSymbolAddress((void**)&phh,  g_hh);
  cudaGetSymbolAddress((void**)&px,   g_x);
  cudaGetSymbolAddress((void**)&pz,   g_z);
  cudaGetSymbolAddress((void**)&pxhi, g_xhi);
  cudaGetSymbolAddress((void**)&pxlo, g_xlo);
  cudaGetSymbolAddress((void**)&pyhi, g_yhi);
  cudaGetSymbolAddress((void**)&pw1hi, g_w1hi);
  cudaGetSymbolAddress((void**)&pw2hi, g_w2hi);
  cudaGetSymbolAddress((void**)&powhi, g_owhi);
  cudaGetSymbolAddress((void**)&pexhi, g_exhi);
  cudaGetSymbolAddress((void**)&pexlo, g_exlo);
  cudaGetSymbolAddress((void**)&pewhi, g_ewhi);
  cudaGetSymbolAddress((void**)&pewlo, g_ewlo);

  static int smem_set = 0;
  if (!smem_set) {
    cudaFuncSetAttribute(mma_gemm<2,3>, cudaFuncAttributeMaxDynamicSharedMemorySize, 2 * 4 * PLANE_B);
    cudaFuncSetAttribute(mma_gemm<1,1>, cudaFuncAttributeMaxDynamicSharedMemorySize, 2 * 2 * PLANE_B);
    cudaFuncSetAttribute(mma_gemm<0,1>, cudaFuncAttributeMaxDynamicSharedMemorySize, 2 * 2 * PLANE_B);
    cudaFuncSetAttribute(mma_gemm<0,2>, cudaFuncAttributeMaxDynamicSharedMemorySize, 2 * 3 * PLANE_B);
    cudaFuncSetAttribute(ctx_split_kernel, cudaFuncAttributeMaxDynamicSharedMemorySize, CTX_SMEM_FLOATS * 4);
    smem_set = 1;
  }
  const int ctx_smem = CTX_SMEM_FLOATS * 4;

  // input conversions (embed deps)
  {
    int n3 = BB * L0 * 64;
    xsplit_kernel<<<(n3 + 255) / 256, 256>>>(x, pexhi, pexlo, n3);
    int n4 = DD * 64;
    xsplit_kernel<<<(n4 + 255) / 256, 256>>>(emb_w, pewhi, pewlo, n4);
  }

  // Embed (3-pass fp16 mma): h = x @ emb_w^T + emb_b + PE; also fp16 mirror
  {
    int M = BB * L0;
    mma_gemm<2,3><<<dim3(DD / 128, M / 128), 256, 2 * 4 * PLANE_B>>>(
        pexhi, pexlo, pewhi, pewlo, emb_b, ph, nullptr, phh, M, DD, 64, L0 - 1);
  }

  int L = L0;
  float* cur = ph;
  for (int i = 0; i < 3; i++) {
    int u = (i == 0) ? 45 : (i == 1) ? 40 : 35;
    int M = BB * L;
    unsigned k0, k1; layer_key(i, k0, k1);
    prob_m_kernel<<<dim3(L / 8, 64), 256>>>(phh, L, u, 1.0f / (float)L,
                                            k0, k1, L - 1);
    topk_kernel<<<64, 256>>>(L, u);
    int nsplit = L / 512; if (nsplit < 1) nsplit = 1; if (nsplit > 8) nsplit = 8;
    ctx_split_kernel<<<dim3(nsplit, 64), 256, ctx_smem>>>(phh, L, u, L / nsplit);
    ctx_merge_kernel<<<64, 256>>>(L, u, nsplit);
    assemble_ln1_kernel<<<M, 128>>>(cur, px, pxhi,
                                    ln1_s + i * DD, ln1_b + i * DD, L, u);

    if (i == 0) {
      int n1 = 3 * DFF * DD;
      whalf_kernel<<<(n1 + 255) / 256, 256>>>(w1, pw1hi, n1);
      whalf_kernel<<<(n1 + 255) / 256, 256>>>(w2, pw2hi, n1);
      int n2 = DD * DD;
      whalf_kernel<<<(n2 + 255) / 256, 256>>>(out_w, powhi, n2);
    }

    // FFN1: y = gelu(x @ w1^T + b1), 1-pass, fp16 out
    mma_gemm<1,1><<<dim3(DFF / 128, M / 128), 256, 2 * 2 * PLANE_B>>>(
        pxhi, nullptr, pw1hi + (size_t)i * DFF * DD, nullptr,
        b1 + i * DFF, nullptr, pyhi, nullptr, M, DFF, DD, 0);
    // FFN2: z = y @ w2^T + b2, 1-pass, fp32 out
    mma_gemm<0,1><<<dim3(DD / 128, M / 128), 256, 2 * 2 * PLANE_B>>>(
        pyhi, nullptr, pw2hi + (size_t)i * DD * DFF, nullptr,
        b2 + i * DD, pz, nullptr, nullptr, M, DD, DFF, 0);

    if (i < 2) {
      int L2 = L / 2;
      ln2_distil_kernel<<<BB * L2, 128>>>(px, pz, cur, phh,
                                          ln2_s + i * DD, ln2_b + i * DD, L2);
      L = L2;
    } else {
      ln2_split_kernel<<<M, 128>>>(px, pz, pxhi, pxlo,
                                   ln2_s + i * DD, ln2_b + i * DD);
    }
  }

  // Final projection: out = h @ out_w^T + out_b, 2-pass A (M=8192,N=512,K=512)
  {
    int M = BB * L;   // L = 1024
    mma_gemm<0,2><<<dim3(DD / 128, M / 128), 256, 2 * 3 * PLANE_B>>>(
        pxhi, pxlo, powhi, nullptr, out_b, out, nullptr, nullptr, M, DD, DD, 0);
  }
}